// round 1
// baseline (speedup 1.0000x reference)
#include <cuda_runtime.h>
#include <math.h>

#define BATCH 2
#define SEQ   4096
#define HID   2048
#define DIM   128
#define TOK   (BATCH*SEQ)     // 8192
#define CHK   128
#define NCB   (SEQ/CHK)       // 32 chunks per batch
#define NC    (BATCH*NCB)     // 64 chunks total
#define EPSV  1e-6f

// ---------------- scratch (static device globals; no allocation) ----------------
__device__ float g_pq[TOK*DIM];          // sigma(q)
__device__ float g_pk[TOK*DIM];          // sigma(k)  (== sk)
__device__ float g_v [TOK*DIM];          // v
__device__ float g_w [TOK*DIM];          // v - v_ret
__device__ float g_outbuf[TOK*DIM];      // gated output (pre out-proj)
__device__ float g_kv[NC*DIM*DIM];       // per-chunk sum  pk^T v
__device__ float g_kvprev[NC*DIM*DIM];   // exclusive prefix (S_prev per chunk)
__device__ float g_mdelta[NC*DIM*DIM];   // per-chunk delta-rule partials
__device__ float g_A[NC*CHK*CHK];        // masked intra-chunk scores
__device__ float g_ks[NC*DIM];           // per-chunk sum pk
__device__ float g_ksprev[NC*DIM];       // exclusive prefix (z_prev per chunk)
__device__ float g_den[TOK];             // intra-chunk row sums of masked A

__device__ __forceinline__ float sigma_f(float x) {
    return (x > 0.f) ? (x + 1.f) : expf(x);   // elu(x)+1
}

// ================= Kernel 1: fused QKV projection (NT GEMM, K=2048) =============
// C[8192, 128] per weight matrix; BM=64, BN=128, BK=16, 128 threads, 8x8 micro.
__global__ __launch_bounds__(128) void qkv_kernel(
    const float* __restrict__ hs, const float* __restrict__ wq,
    const float* __restrict__ wk, const float* __restrict__ wv)
{
    __shared__ float As[16][68];    // [k][m]
    __shared__ float Bs[16][132];   // [k][n]
    const int m0 = blockIdx.x * 64;
    const int nt = blockIdx.y;                   // 0=q,1=k,2=v
    const float* Wp = (nt == 0) ? wq : (nt == 1) ? wk : wv;
    const int tid = threadIdx.x;
    const int ty = tid >> 4, tx = tid & 15;
    float acc[8][8];
    #pragma unroll
    for (int i = 0; i < 8; i++)
        #pragma unroll
        for (int j = 0; j < 8; j++) acc[i][j] = 0.f;

    for (int k0 = 0; k0 < HID; k0 += 16) {
        #pragma unroll
        for (int it = 0; it < 2; it++) {
            int t = tid * 2 + it, ml = t >> 2, kl = (t & 3) * 4;
            float4 v = *(const float4*)(hs + (size_t)(m0 + ml) * HID + k0 + kl);
            As[kl+0][ml] = v.x; As[kl+1][ml] = v.y; As[kl+2][ml] = v.z; As[kl+3][ml] = v.w;
        }
        #pragma unroll
        for (int it = 0; it < 4; it++) {
            int t = tid * 4 + it, nl = t >> 2, kl = (t & 3) * 4;
            float4 v = *(const float4*)(Wp + (size_t)nl * HID + k0 + kl);
            Bs[kl+0][nl] = v.x; Bs[kl+1][nl] = v.y; Bs[kl+2][nl] = v.z; Bs[kl+3][nl] = v.w;
        }
        __syncthreads();
        #pragma unroll
        for (int kk = 0; kk < 16; kk++) {
            float a[8], b[8];
            *(float4*)(a)     = *(const float4*)&As[kk][ty*8];
            *(float4*)(a + 4) = *(const float4*)&As[kk][ty*8 + 4];
            *(float4*)(b)     = *(const float4*)&Bs[kk][tx*8];
            *(float4*)(b + 4) = *(const float4*)&Bs[kk][tx*8 + 4];
            #pragma unroll
            for (int i = 0; i < 8; i++)
                #pragma unroll
                for (int j = 0; j < 8; j++)
                    acc[i][j] = fmaf(a[i], b[j], acc[i][j]);
        }
        __syncthreads();
    }
    float* dst = (nt == 0) ? g_pq : (nt == 1) ? g_pk : g_v;
    #pragma unroll
    for (int i = 0; i < 8; i++) {
        int m = m0 + ty * 8 + i;
        float o[8];
        #pragma unroll
        for (int j = 0; j < 8; j++) {
            float x = acc[i][j];
            o[j] = (nt < 2) ? sigma_f(x) : x;
        }
        *(float4*)(dst + (size_t)m * DIM + tx*8)     = *(float4*)(o);
        *(float4*)(dst + (size_t)m * DIM + tx*8 + 4) = *(float4*)(o + 4);
    }
}

// ===== Kernel 2: per-chunk outer sums  C[d,e] = sum_s pk[s,d]*B[s,e] (K=s=128) ===
// mode 0: B=v -> g_kv (+ g_ks column sums).  mode 1: B=g_w -> g_mdelta.
__global__ __launch_bounds__(256) void chunk_outer_kernel(int mode)
{
    __shared__ float Ps[16][132];
    __shared__ float Vs[16][132];
    const int c = blockIdx.x;
    const float* Ac = g_pk + (size_t)c * CHK * DIM;
    const float* Bc = ((mode == 0) ? g_v : g_w) + (size_t)c * CHK * DIM;
    float* Cout = (mode == 0) ? g_kv : g_mdelta;
    const int tid = threadIdx.x;
    const int ty = tid >> 4, tx = tid & 15;
    float acc[8][8]; float ks[8];
    #pragma unroll
    for (int i = 0; i < 8; i++) { ks[i] = 0.f;
        #pragma unroll
        for (int j = 0; j < 8; j++) acc[i][j] = 0.f; }

    for (int s0 = 0; s0 < CHK; s0 += 16) {
        #pragma unroll
        for (int it = 0; it < 2; it++) {
            int t = tid * 2 + it, sl = t >> 5, dl = (t & 31) * 4;
            *(float4*)&Ps[sl][dl] = *(const float4*)(Ac + (size_t)(s0 + sl) * DIM + dl);
            *(float4*)&Vs[sl][dl] = *(const float4*)(Bc + (size_t)(s0 + sl) * DIM + dl);
        }
        __syncthreads();
        #pragma unroll
        for (int ss = 0; ss < 16; ss++) {
            float a[8], b[8];
            *(float4*)(a)     = *(const float4*)&Ps[ss][ty*8];
            *(float4*)(a + 4) = *(const float4*)&Ps[ss][ty*8 + 4];
            *(float4*)(b)     = *(const float4*)&Vs[ss][tx*8];
            *(float4*)(b + 4) = *(const float4*)&Vs[ss][tx*8 + 4];
            #pragma unroll
            for (int i = 0; i < 8; i++) {
                ks[i] += a[i];
                #pragma unroll
                for (int j = 0; j < 8; j++)
                    acc[i][j] = fmaf(a[i], b[j], acc[i][j]);
            }
        }
        __syncthreads();
    }
    float* C = Cout + (size_t)c * DIM * DIM;
    #pragma unroll
    for (int i = 0; i < 8; i++) {
        *(float4*)(C + (size_t)(ty*8 + i) * DIM + tx*8)     = *(float4*)(acc[i]);
        *(float4*)(C + (size_t)(ty*8 + i) * DIM + tx*8 + 4) = *(float4*)(acc[i] + 4);
    }
    if (mode == 0 && tx == 0) {
        #pragma unroll
        for (int i = 0; i < 8; i++) g_ks[c * DIM + ty*8 + i] = ks[i];
    }
}

// =========== Kernel 3a/3b: exclusive prefix scans over chunks (per batch) =======
__global__ void scan_kv_kernel()
{
    int p = blockIdx.x * blockDim.x + threadIdx.x;   // 0..16383
    int b = blockIdx.y;
    size_t base = (size_t)b * NCB * DIM * DIM + p;
    float run = 0.f;
    for (int cc = 0; cc < NCB; cc++) {
        size_t idx = base + (size_t)cc * DIM * DIM;
        float t = g_kv[idx];
        g_kvprev[idx] = run;
        run += t;
    }
}
__global__ void scan_ks_kernel()
{
    int d = threadIdx.x;  // 128
    int b = blockIdx.x;
    float run = 0.f;
    for (int cc = 0; cc < NCB; cc++) {
        int idx = (b * NCB + cc) * DIM + d;
        g_ksprev[idx] = run;
        run += g_ks[idx];
    }
}

// ====== Kernel 4: intra-chunk scores A = mask(PQ PK^T), rowsums -> g_den ========
__global__ __launch_bounds__(256) void scores_kernel()
{
    __shared__ float Qs[16][132];   // [d][t]
    __shared__ float Ks[16][132];   // [d][s]
    __shared__ float red[128][17];
    const int c = blockIdx.x;
    const float* Q = g_pq + (size_t)c * CHK * DIM;
    const float* K = g_pk + (size_t)c * CHK * DIM;
    const int tid = threadIdx.x;
    const int ty = tid >> 4, tx = tid & 15;
    float acc[8][8];
    #pragma unroll
    for (int i = 0; i < 8; i++)
        #pragma unroll
        for (int j = 0; j < 8; j++) acc[i][j] = 0.f;

    for (int d0 = 0; d0 < DIM; d0 += 16) {
        #pragma unroll
        for (int it = 0; it < 2; it++) {
            int t = tid * 2 + it, tl = t >> 2, dl = (t & 3) * 4;
            float4 v = *(const float4*)(Q + (size_t)tl * DIM + d0 + dl);
            Qs[dl+0][tl] = v.x; Qs[dl+1][tl] = v.y; Qs[dl+2][tl] = v.z; Qs[dl+3][tl] = v.w;
            float4 w = *(const float4*)(K + (size_t)tl * DIM + d0 + dl);
            Ks[dl+0][tl] = w.x; Ks[dl+1][tl] = w.y; Ks[dl+2][tl] = w.z; Ks[dl+3][tl] = w.w;
        }
        __syncthreads();
        #pragma unroll
        for (int dd = 0; dd < 16; dd++) {
            float a[8], b[8];
            *(float4*)(a)     = *(const float4*)&Qs[dd][ty*8];
            *(float4*)(a + 4) = *(const float4*)&Qs[dd][ty*8 + 4];
            *(float4*)(b)     = *(const float4*)&Ks[dd][tx*8];
            *(float4*)(b + 4) = *(const float4*)&Ks[dd][tx*8 + 4];
            #pragma unroll
            for (int i = 0; i < 8; i++)
                #pragma unroll
                for (int j = 0; j < 8; j++)
                    acc[i][j] = fmaf(a[i], b[j], acc[i][j]);
        }
        __syncthreads();
    }
    float* Ao = g_A + (size_t)c * CHK * CHK;
    #pragma unroll
    for (int i = 0; i < 8; i++) {
        int t = ty * 8 + i;
        float rs = 0.f, o[8];
        #pragma unroll
        for (int j = 0; j < 8; j++) {
            int s = tx * 8 + j;
            float x = (s <= t) ? acc[i][j] : 0.f;   // inclusive causal mask
            o[j] = x; rs += x;
        }
        *(float4*)(Ao + (size_t)t * CHK + tx*8)     = *(float4*)(o);
        *(float4*)(Ao + (size_t)t * CHK + tx*8 + 4) = *(float4*)(o + 4);
        red[t][tx] = rs;
    }
    __syncthreads();
    if (tid < 128) {
        float s = 0.f;
        #pragma unroll
        for (int x = 0; x < 16; x++) s += red[tid][x];
        g_den[c * CHK + tid] = s;
    }
}

// ==== Kernel 5: per-chunk gated output (local linear attn + compressive mem) ====
// tile: 128 tokens x 64 e-cols; grid (NC, 2); 128 threads; dual 8x8 accumulators.
__global__ __launch_bounds__(128) void output_kernel(
    const float* __restrict__ Min, const float* __restrict__ zin,
    const float* __restrict__ gate)
{
    __shared__ float Ts[16][132];   // transposed A or PQ: [k][t]
    __shared__ float B1[16][68];    // V tile / S_prev tile
    __shared__ float B2[16][68];    // M tile
    __shared__ float Zp[16], Zz[16];
    const int c = blockIdx.x;
    const int eo = blockIdx.y * 64;
    const int tid = threadIdx.x;
    const int ty = tid >> 3, tx = tid & 7;
    float accL[8][8], accM[8][8], denI[8], denM[8];
    #pragma unroll
    for (int i = 0; i < 8; i++) { denI[i] = 0.f; denM[i] = 0.f;
        #pragma unroll
        for (int j = 0; j < 8; j++) { accL[i][j] = 0.f; accM[i][j] = 0.f; } }

    // ---- phase 1: accL += A_masked @ V  (K = s) ----
    const float* Ac = g_A + (size_t)c * CHK * CHK;
    const float* Vc = g_v + (size_t)c * CHK * DIM + eo;
    for (int s0 = 0; s0 < CHK; s0 += 16) {
        #pragma unroll
        for (int it = 0; it < 4; it++) {
            int t = tid * 4 + it, tl = t >> 2, sl = (t & 3) * 4;
            float4 v = *(const float4*)(Ac + (size_t)tl * CHK + s0 + sl);
            Ts[sl+0][tl] = v.x; Ts[sl+1][tl] = v.y; Ts[sl+2][tl] = v.z; Ts[sl+3][tl] = v.w;
        }
        #pragma unroll
        for (int it = 0; it < 2; it++) {
            int t = tid * 2 + it, sl = t >> 4, el = (t & 15) * 4;
            *(float4*)&B1[sl][el] = *(const float4*)(Vc + (size_t)(s0 + sl) * DIM + el);
        }
        __syncthreads();
        #pragma unroll
        for (int ss = 0; ss < 16; ss++) {
            float a[8], b[8];
            *(float4*)(a)     = *(const float4*)&Ts[ss][ty*8];
            *(float4*)(a + 4) = *(const float4*)&Ts[ss][ty*8 + 4];
            *(float4*)(b)     = *(const float4*)&B1[ss][tx*8];
            *(float4*)(b + 4) = *(const float4*)&B1[ss][tx*8 + 4];
            #pragma unroll
            for (int i = 0; i < 8; i++)
                #pragma unroll
                for (int j = 0; j < 8; j++)
                    accL[i][j] = fmaf(a[i], b[j], accL[i][j]);
        }
        __syncthreads();
    }
    // ---- phase 2: accL += PQ@S_prev; accM += PQ@M; denI += PQ.z_prev; denM += PQ.z
    const float* Qc = g_pq + (size_t)c * CHK * DIM;
    const float* Sp = g_kvprev + (size_t)c * DIM * DIM + eo;
    const float* Mp = Min + eo;
    const float* zp = g_ksprev + (size_t)c * DIM;
    for (int d0 = 0; d0 < DIM; d0 += 16) {
        #pragma unroll
        for (int it = 0; it < 4; it++) {
            int t = tid * 4 + it, tl = t >> 2, dl = (t & 3) * 4;
            float4 v = *(const float4*)(Qc + (size_t)tl * DIM + d0 + dl);
            Ts[dl+0][tl] = v.x; Ts[dl+1][tl] = v.y; Ts[dl+2][tl] = v.z; Ts[dl+3][tl] = v.w;
        }
        #pragma unroll
        for (int it = 0; it < 2; it++) {
            int t = tid * 2 + it, dl = t >> 4, el = (t & 15) * 4;
            *(float4*)&B1[dl][el] = *(const float4*)(Sp + (size_t)(d0 + dl) * DIM + el);
            *(float4*)&B2[dl][el] = *(const float4*)(Mp + (size_t)(d0 + dl) * DIM + el);
        }
        if (tid < 16) { Zp[tid] = zp[d0 + tid]; Zz[tid] = zin[d0 + tid]; }
        __syncthreads();
        #pragma unroll
        for (int dd = 0; dd < 16; dd++) {
            float a[8], bs[8], bm[8];
            *(float4*)(a)      = *(const float4*)&Ts[dd][ty*8];
            *(float4*)(a + 4)  = *(const float4*)&Ts[dd][ty*8 + 4];
            *(float4*)(bs)     = *(const float4*)&B1[dd][tx*8];
            *(float4*)(bs + 4) = *(const float4*)&B1[dd][tx*8 + 4];
            *(float4*)(bm)     = *(const float4*)&B2[dd][tx*8];
            *(float4*)(bm + 4) = *(const float4*)&B2[dd][tx*8 + 4];
            float zpv = Zp[dd], zzv = Zz[dd];
            #pragma unroll
            for (int i = 0; i < 8; i++) {
                denI[i] = fmaf(a[i], zpv, denI[i]);
                denM[i] = fmaf(a[i], zzv, denM[i]);
                #pragma unroll
                for (int j = 0; j < 8; j++) {
                    accL[i][j] = fmaf(a[i], bs[j], accL[i][j]);
                    accM[i][j] = fmaf(a[i], bm[j], accM[i][j]);
                }
            }
        }
        __syncthreads();
    }
    float gv = 1.f / (1.f + expf(-gate[0]));
    #pragma unroll
    for (int i = 0; i < 8; i++) {
        int tg = c * CHK + ty * 8 + i;
        float den  = g_den[tg] + denI[i] + EPSV;
        float mden = denM[i] + EPSV;
        float rl = (1.f - gv) / den, rm = gv / mden;
        float o[8];
        #pragma unroll
        for (int j = 0; j < 8; j++)
            o[j] = rm * accM[i][j] + rl * accL[i][j];
        *(float4*)(g_outbuf + (size_t)tg * DIM + eo + tx*8)     = *(float4*)(o);
        *(float4*)(g_outbuf + (size_t)tg * DIM + eo + tx*8 + 4) = *(float4*)(o + 4);
    }
}

// ======= Kernel 6: W = v - (PK@M)/(PK.z + eps)  (delta-rule retrieval) ==========
__global__ __launch_bounds__(128) void vret_kernel(
    const float* __restrict__ Min, const float* __restrict__ zin)
{
    __shared__ float Ts[16][132];
    __shared__ float B2[16][68];
    __shared__ float Zz[16];
    const int c = blockIdx.x;
    const int eo = blockIdx.y * 64;
    const int tid = threadIdx.x;
    const int ty = tid >> 3, tx = tid & 7;
    float acc[8][8], denV[8];
    #pragma unroll
    for (int i = 0; i < 8; i++) { denV[i] = 0.f;
        #pragma unroll
        for (int j = 0; j < 8; j++) acc[i][j] = 0.f; }

    const float* Kc = g_pk + (size_t)c * CHK * DIM;
    const float* Mp = Min + eo;
    for (int d0 = 0; d0 < DIM; d0 += 16) {
        #pragma unroll
        for (int it = 0; it < 4; it++) {
            int t = tid * 4 + it, tl = t >> 2, dl = (t & 3) * 4;
            float4 v = *(const float4*)(Kc + (size_t)tl * DIM + d0 + dl);
            Ts[dl+0][tl] = v.x; Ts[dl+1][tl] = v.y; Ts[dl+2][tl] = v.z; Ts[dl+3][tl] = v.w;
        }
        #pragma unroll
        for (int it = 0; it < 2; it++) {
            int t = tid * 2 + it, dl = t >> 4, el = (t & 15) * 4;
            *(float4*)&B2[dl][el] = *(const float4*)(Mp + (size_t)(d0 + dl) * DIM + el);
        }
        if (tid < 16) Zz[tid] = zin[d0 + tid];
        __syncthreads();
        #pragma unroll
        for (int dd = 0; dd < 16; dd++) {
            float a[8], bm[8];
            *(float4*)(a)      = *(const float4*)&Ts[dd][ty*8];
            *(float4*)(a + 4)  = *(const float4*)&Ts[dd][ty*8 + 4];
            *(float4*)(bm)     = *(const float4*)&B2[dd][tx*8];
            *(float4*)(bm + 4) = *(const float4*)&B2[dd][tx*8 + 4];
            float zzv = Zz[dd];
            #pragma unroll
            for (int i = 0; i < 8; i++) {
                denV[i] = fmaf(a[i], zzv, denV[i]);
                #pragma unroll
                for (int j = 0; j < 8; j++)
                    acc[i][j] = fmaf(a[i], bm[j], acc[i][j]);
            }
        }
        __syncthreads();
    }
    #pragma unroll
    for (int i = 0; i < 8; i++) {
        int tg = c * CHK + ty * 8 + i;
        float inv = 1.f / (denV[i] + EPSV);
        float4 v0 = *(const float4*)(g_v + (size_t)tg * DIM + eo + tx*8);
        float4 v1 = *(const float4*)(g_v + (size_t)tg * DIM + eo + tx*8 + 4);
        float o[8];
        o[0] = v0.x - acc[i][0]*inv; o[1] = v0.y - acc[i][1]*inv;
        o[2] = v0.z - acc[i][2]*inv; o[3] = v0.w - acc[i][3]*inv;
        o[4] = v1.x - acc[i][4]*inv; o[5] = v1.y - acc[i][5]*inv;
        o[6] = v1.z - acc[i][6]*inv; o[7] = v1.w - acc[i][7]*inv;
        *(float4*)(g_w + (size_t)tg * DIM + eo + tx*8)     = *(float4*)(o);
        *(float4*)(g_w + (size_t)tg * DIM + eo + tx*8 + 4) = *(float4*)(o + 4);
    }
}

// ============ Kernel 7: finalize M_new, z_new (deterministic reduction) =========
__global__ void finalize_kernel(const float* __restrict__ Min,
                                const float* __restrict__ zin,
                                float* __restrict__ outM, float* __restrict__ outZ)
{
    int p = blockIdx.x * 256 + threadIdx.x;   // 0..16383
    float s = Min[p];
    for (int cc = 0; cc < NC; cc++) s += g_mdelta[(size_t)cc * DIM * DIM + p];
    outM[p] = s;
    if (p < DIM) {
        float sz = zin[p];
        for (int cc = 0; cc < NC; cc++) sz += g_ks[cc * DIM + p];
        outZ[p] = sz;
    }
}

// ================= Kernel 8: output projection (NT GEMM, K=128) =================
__global__ __launch_bounds__(128) void outproj_kernel(
    const float* __restrict__ wo, float* __restrict__ out)
{
    __shared__ float As[16][68];
    __shared__ float Bs[16][132];
    const int m0 = blockIdx.x * 64;
    const int n0 = blockIdx.y * 128;
    const int tid = threadIdx.x;
    const int ty = tid >> 4, tx = tid & 15;
    float acc[8][8];
    #pragma unroll
    for (int i = 0; i < 8; i++)
        #pragma unroll
        for (int j = 0; j < 8; j++) acc[i][j] = 0.f;

    for (int k0 = 0; k0 < DIM; k0 += 16) {
        #pragma unroll
        for (int it = 0; it < 2; it++) {
            int t = tid * 2 + it, ml = t >> 2, kl = (t & 3) * 4;
            float4 v = *(const float4*)(g_outbuf + (size_t)(m0 + ml) * DIM + k0 + kl);
            As[kl+0][ml] = v.x; As[kl+1][ml] = v.y; As[kl+2][ml] = v.z; As[kl+3][ml] = v.w;
        }
        #pragma unroll
        for (int it = 0; it < 4; it++) {
            int t = tid * 4 + it, nl = t >> 2, kl = (t & 3) * 4;
            float4 v = *(const float4*)(wo + (size_t)(n0 + nl) * DIM + k0 + kl);
            Bs[kl+0][nl] = v.x; Bs[kl+1][nl] = v.y; Bs[kl+2][nl] = v.z; Bs[kl+3][nl] = v.w;
        }
        __syncthreads();
        #pragma unroll
        for (int kk = 0; kk < 16; kk++) {
            float a[8], b[8];
            *(float4*)(a)     = *(const float4*)&As[kk][ty*8];
            *(float4*)(a + 4) = *(const float4*)&As[kk][ty*8 + 4];
            *(float4*)(b)     = *(const float4*)&Bs[kk][tx*8];
            *(float4*)(b + 4) = *(const float4*)&Bs[kk][tx*8 + 4];
            #pragma unroll
            for (int i = 0; i < 8; i++)
                #pragma unroll
                for (int j = 0; j < 8; j++)
                    acc[i][j] = fmaf(a[i], b[j], acc[i][j]);
        }
        __syncthreads();
    }
    #pragma unroll
    for (int i = 0; i < 8; i++) {
        int m = m0 + ty * 8 + i;
        *(float4*)(out + (size_t)m * HID + n0 + tx*8)     = *(float4*)(acc[i]);
        *(float4*)(out + (size_t)m * HID + n0 + tx*8 + 4) = *(float4*)(acc[i] + 4);
    }
}

// =================================== launch =====================================
extern "C" void kernel_launch(void* const* d_in, const int* in_sizes, int n_in,
                              void* d_out, int out_size)
{
    const float* hs   = (const float*)d_in[0];
    const float* wq   = (const float*)d_in[1];
    const float* wk   = (const float*)d_in[2];
    const float* wv   = (const float*)d_in[3];
    const float* wo   = (const float*)d_in[4];
    const float* gate = (const float*)d_in[5];
    const float* M    = (const float*)d_in[6];
    const float* z    = (const float*)d_in[7];
    float* out  = (float*)d_out;
    float* outM = out + (size_t)TOK * HID;
    float* outZ = outM + DIM * DIM;

    qkv_kernel<<<dim3(TOK/64, 3), 128>>>(hs, wq, wk, wv);
    chunk_outer_kernel<<<NC, 256>>>(0);                       // g_kv, g_ks
    scan_kv_kernel<<<dim3(64, BATCH), 256>>>();               // S_prev
    scan_ks_kernel<<<BATCH, 128>>>();                         // z_prev
    scores_kernel<<<NC, 256>>>();                             // g_A, g_den
    output_kernel<<<dim3(NC, 2), 128>>>(M, z, gate);          // g_outbuf
    vret_kernel<<<dim3(NC, 2), 128>>>(M, z);                  // g_w
    chunk_outer_kernel<<<NC, 256>>>(1);                       // g_mdelta
    finalize_kernel<<<64, 256>>>(M, z, outM, outZ);           // M_new, z_new
    outproj_kernel<<<dim3(TOK/64, HID/128), 128>>>(wo, out);  // out
}

// round 2
// speedup vs baseline: 1.6119x; 1.6119x over previous
#include <cuda_runtime.h>
#include <math.h>

#define BATCH 2
#define SEQ   4096
#define HID   2048
#define DIM   128
#define TOK   (BATCH*SEQ)     // 8192
#define CHK   128
#define NCB   (SEQ/CHK)       // 32 chunks per batch
#define NC    (BATCH*NCB)     // 64 chunks total
#define EPSV  1e-6f

// ---------------- scratch (static device globals; no allocation) ----------------
__device__ float g_pq[TOK*DIM];          // sigma(q)
__device__ float g_pk[TOK*DIM];          // sigma(k)  (== sk)
__device__ float g_v [TOK*DIM];          // v
__device__ float g_w [TOK*DIM];          // v - v_ret
__device__ float g_outbuf[TOK*DIM];      // gated output (pre out-proj)
__device__ float g_kv[NC*DIM*DIM];       // per-chunk sum  pk^T v
__device__ float g_kvprev[NC*DIM*DIM];   // exclusive prefix (S_prev per chunk)
__device__ float g_mdelta[NC*DIM*DIM];   // per-chunk delta-rule partials
__device__ float g_A[NC*CHK*CHK];        // masked intra-chunk scores
__device__ float g_ks[NC*DIM];           // per-chunk sum pk
__device__ float g_ksprev[NC*DIM];       // exclusive prefix (z_prev per chunk)
__device__ float g_den[TOK];             // intra-chunk row sums of masked A

__device__ __forceinline__ float sigma_f(float x) {
    return (x > 0.f) ? (x + 1.f) : expf(x);   // elu(x)+1
}

// ================= Kernel 1: fused QKV projection (NT GEMM, K=2048) =============
// C[8192, 128] per weight matrix; BM=64, BN=128, BK=16, 128 threads, 8x8 micro.
__global__ __launch_bounds__(128) void qkv_kernel(
    const float* __restrict__ hs, const float* __restrict__ wq,
    const float* __restrict__ wk, const float* __restrict__ wv)
{
    __shared__ float As[16][68];    // [k][m]
    __shared__ float Bs[16][132];   // [k][n]
    const int m0 = blockIdx.x * 64;
    const int nt = blockIdx.y;                   // 0=q,1=k,2=v
    const float* Wp = (nt == 0) ? wq : (nt == 1) ? wk : wv;
    const int tid = threadIdx.x;
    const int ty = tid >> 4, tx = tid & 15;
    float acc[8][8];
    #pragma unroll
    for (int i = 0; i < 8; i++)
        #pragma unroll
        for (int j = 0; j < 8; j++) acc[i][j] = 0.f;

    for (int k0 = 0; k0 < HID; k0 += 16) {
        #pragma unroll
        for (int it = 0; it < 2; it++) {
            int t = tid * 2 + it, ml = t >> 2, kl = (t & 3) * 4;
            float4 v = *(const float4*)(hs + (size_t)(m0 + ml) * HID + k0 + kl);
            As[kl+0][ml] = v.x; As[kl+1][ml] = v.y; As[kl+2][ml] = v.z; As[kl+3][ml] = v.w;
        }
        #pragma unroll
        for (int it = 0; it < 4; it++) {
            int t = tid * 4 + it, nl = t >> 2, kl = (t & 3) * 4;
            float4 v = *(const float4*)(Wp + (size_t)nl * HID + k0 + kl);
            Bs[kl+0][nl] = v.x; Bs[kl+1][nl] = v.y; Bs[kl+2][nl] = v.z; Bs[kl+3][nl] = v.w;
        }
        __syncthreads();
        #pragma unroll
        for (int kk = 0; kk < 16; kk++) {
            float a[8], b[8];
            *(float4*)(a)     = *(const float4*)&As[kk][ty*8];
            *(float4*)(a + 4) = *(const float4*)&As[kk][ty*8 + 4];
            *(float4*)(b)     = *(const float4*)&Bs[kk][tx*8];
            *(float4*)(b + 4) = *(const float4*)&Bs[kk][tx*8 + 4];
            #pragma unroll
            for (int i = 0; i < 8; i++)
                #pragma unroll
                for (int j = 0; j < 8; j++)
                    acc[i][j] = fmaf(a[i], b[j], acc[i][j]);
        }
        __syncthreads();
    }
    float* dst = (nt == 0) ? g_pq : (nt == 1) ? g_pk : g_v;
    #pragma unroll
    for (int i = 0; i < 8; i++) {
        int m = m0 + ty * 8 + i;
        float o[8];
        #pragma unroll
        for (int j = 0; j < 8; j++) {
            float x = acc[i][j];
            o[j] = (nt < 2) ? sigma_f(x) : x;
        }
        *(float4*)(dst + (size_t)m * DIM + tx*8)     = *(float4*)(o);
        *(float4*)(dst + (size_t)m * DIM + tx*8 + 4) = *(float4*)(o + 4);
    }
}

// ===== Kernel 2: per-chunk outer sums  C[d,e] = sum_s pk[s,d]*B[s,e] (K=s=128) ===
// mode 0: B=v -> g_kv (+ g_ks column sums).  mode 1: B=g_w -> g_mdelta.
__global__ __launch_bounds__(256) void chunk_outer_kernel(int mode)
{
    __shared__ float Ps[16][132];
    __shared__ float Vs[16][132];
    const int c = blockIdx.x;
    const float* Ac = g_pk + (size_t)c * CHK * DIM;
    const float* Bc = ((mode == 0) ? g_v : g_w) + (size_t)c * CHK * DIM;
    float* Cout = (mode == 0) ? g_kv : g_mdelta;
    const int tid = threadIdx.x;
    const int ty = tid >> 4, tx = tid & 15;
    float acc[8][8]; float ks[8];
    #pragma unroll
    for (int i = 0; i < 8; i++) { ks[i] = 0.f;
        #pragma unroll
        for (int j = 0; j < 8; j++) acc[i][j] = 0.f; }

    for (int s0 = 0; s0 < CHK; s0 += 16) {
        #pragma unroll
        for (int it = 0; it < 2; it++) {
            int t = tid * 2 + it, sl = t >> 5, dl = (t & 31) * 4;
            *(float4*)&Ps[sl][dl] = *(const float4*)(Ac + (size_t)(s0 + sl) * DIM + dl);
            *(float4*)&Vs[sl][dl] = *(const float4*)(Bc + (size_t)(s0 + sl) * DIM + dl);
        }
        __syncthreads();
        #pragma unroll
        for (int ss = 0; ss < 16; ss++) {
            float a[8], b[8];
            *(float4*)(a)     = *(const float4*)&Ps[ss][ty*8];
            *(float4*)(a + 4) = *(const float4*)&Ps[ss][ty*8 + 4];
            *(float4*)(b)     = *(const float4*)&Vs[ss][tx*8];
            *(float4*)(b + 4) = *(const float4*)&Vs[ss][tx*8 + 4];
            #pragma unroll
            for (int i = 0; i < 8; i++) {
                ks[i] += a[i];
                #pragma unroll
                for (int j = 0; j < 8; j++)
                    acc[i][j] = fmaf(a[i], b[j], acc[i][j]);
            }
        }
        __syncthreads();
    }
    float* C = Cout + (size_t)c * DIM * DIM;
    #pragma unroll
    for (int i = 0; i < 8; i++) {
        *(float4*)(C + (size_t)(ty*8 + i) * DIM + tx*8)     = *(float4*)(acc[i]);
        *(float4*)(C + (size_t)(ty*8 + i) * DIM + tx*8 + 4) = *(float4*)(acc[i] + 4);
    }
    if (mode == 0 && tx == 0) {
        #pragma unroll
        for (int i = 0; i < 8; i++) g_ks[c * DIM + ty*8 + i] = ks[i];
    }
}

// =========== Kernel 3a/3b: exclusive prefix scans over chunks (per batch) =======
__global__ void scan_kv_kernel()
{
    int p = blockIdx.x * blockDim.x + threadIdx.x;   // 0..16383
    int b = blockIdx.y;
    size_t base = (size_t)b * NCB * DIM * DIM + p;
    float run = 0.f;
    for (int cc = 0; cc < NCB; cc++) {
        size_t idx = base + (size_t)cc * DIM * DIM;
        float t = g_kv[idx];
        g_kvprev[idx] = run;
        run += t;
    }
}
__global__ void scan_ks_kernel()
{
    int d = threadIdx.x;  // 128
    int b = blockIdx.x;
    float run = 0.f;
    for (int cc = 0; cc < NCB; cc++) {
        int idx = (b * NCB + cc) * DIM + d;
        g_ksprev[idx] = run;
        run += g_ks[idx];
    }
}

// ====== Kernel 4: intra-chunk scores A = mask(PQ PK^T), rowsums -> g_den ========
__global__ __launch_bounds__(256) void scores_kernel()
{
    __shared__ float Qs[16][132];   // [d][t]
    __shared__ float Ks[16][132];   // [d][s]
    __shared__ float red[128][17];
    const int c = blockIdx.x;
    const float* Q = g_pq + (size_t)c * CHK * DIM;
    const float* K = g_pk + (size_t)c * CHK * DIM;
    const int tid = threadIdx.x;
    const int ty = tid >> 4, tx = tid & 15;
    float acc[8][8];
    #pragma unroll
    for (int i = 0; i < 8; i++)
        #pragma unroll
        for (int j = 0; j < 8; j++) acc[i][j] = 0.f;

    for (int d0 = 0; d0 < DIM; d0 += 16) {
        #pragma unroll
        for (int it = 0; it < 2; it++) {
            int t = tid * 2 + it, tl = t >> 2, dl = (t & 3) * 4;
            float4 v = *(const float4*)(Q + (size_t)tl * DIM + d0 + dl);
            Qs[dl+0][tl] = v.x; Qs[dl+1][tl] = v.y; Qs[dl+2][tl] = v.z; Qs[dl+3][tl] = v.w;
            float4 w = *(const float4*)(K + (size_t)tl * DIM + d0 + dl);
            Ks[dl+0][tl] = w.x; Ks[dl+1][tl] = w.y; Ks[dl+2][tl] = w.z; Ks[dl+3][tl] = w.w;
        }
        __syncthreads();
        #pragma unroll
        for (int dd = 0; dd < 16; dd++) {
            float a[8], b[8];
            *(float4*)(a)     = *(const float4*)&Qs[dd][ty*8];
            *(float4*)(a + 4) = *(const float4*)&Qs[dd][ty*8 + 4];
            *(float4*)(b)     = *(const float4*)&Ks[dd][tx*8];
            *(float4*)(b + 4) = *(const float4*)&Ks[dd][tx*8 + 4];
            #pragma unroll
            for (int i = 0; i < 8; i++)
                #pragma unroll
                for (int j = 0; j < 8; j++)
                    acc[i][j] = fmaf(a[i], b[j], acc[i][j]);
        }
        __syncthreads();
    }
    float* Ao = g_A + (size_t)c * CHK * CHK;
    #pragma unroll
    for (int i = 0; i < 8; i++) {
        int t = ty * 8 + i;
        float rs = 0.f, o[8];
        #pragma unroll
        for (int j = 0; j < 8; j++) {
            int s = tx * 8 + j;
            float x = (s <= t) ? acc[i][j] : 0.f;   // inclusive causal mask
            o[j] = x; rs += x;
        }
        *(float4*)(Ao + (size_t)t * CHK + tx*8)     = *(float4*)(o);
        *(float4*)(Ao + (size_t)t * CHK + tx*8 + 4) = *(float4*)(o + 4);
        red[t][tx] = rs;
    }
    __syncthreads();
    if (tid < 128) {
        float s = 0.f;
        #pragma unroll
        for (int x = 0; x < 16; x++) s += red[tid][x];
        g_den[c * CHK + tid] = s;
    }
}

// ==== Kernel 5: per-chunk gated output (local linear attn + compressive mem) ====
// tile: 128 tokens x 64 e-cols; grid (NC, 2); 128 threads; dual 8x8 accumulators.
__global__ __launch_bounds__(128) void output_kernel(
    const float* __restrict__ Min, const float* __restrict__ zin,
    const float* __restrict__ gate)
{
    __shared__ float Ts[16][132];   // transposed A or PQ: [k][t]
    __shared__ float B1[16][68];    // V tile / S_prev tile
    __shared__ float B2[16][68];    // M tile
    __shared__ float Zp[16], Zz[16];
    const int c = blockIdx.x;
    const int eo = blockIdx.y * 64;
    const int tid = threadIdx.x;
    const int ty = tid >> 3, tx = tid & 7;
    float accL[8][8], accM[8][8], denI[8], denM[8];
    #pragma unroll
    for (int i = 0; i < 8; i++) { denI[i] = 0.f; denM[i] = 0.f;
        #pragma unroll
        for (int j = 0; j < 8; j++) { accL[i][j] = 0.f; accM[i][j] = 0.f; } }

    // ---- phase 1: accL += A_masked @ V  (K = s) ----
    const float* Ac = g_A + (size_t)c * CHK * CHK;
    const float* Vc = g_v + (size_t)c * CHK * DIM + eo;
    for (int s0 = 0; s0 < CHK; s0 += 16) {
        #pragma unroll
        for (int it = 0; it < 4; it++) {
            int t = tid * 4 + it, tl = t >> 2, sl = (t & 3) * 4;
            float4 v = *(const float4*)(Ac + (size_t)tl * CHK + s0 + sl);
            Ts[sl+0][tl] = v.x; Ts[sl+1][tl] = v.y; Ts[sl+2][tl] = v.z; Ts[sl+3][tl] = v.w;
        }
        #pragma unroll
        for (int it = 0; it < 2; it++) {
            int t = tid * 2 + it, sl = t >> 4, el = (t & 15) * 4;
            *(float4*)&B1[sl][el] = *(const float4*)(Vc + (size_t)(s0 + sl) * DIM + el);
        }
        __syncthreads();
        #pragma unroll
        for (int ss = 0; ss < 16; ss++) {
            float a[8], b[8];
            *(float4*)(a)     = *(const float4*)&Ts[ss][ty*8];
            *(float4*)(a + 4) = *(const float4*)&Ts[ss][ty*8 + 4];
            *(float4*)(b)     = *(const float4*)&B1[ss][tx*8];
            *(float4*)(b + 4) = *(const float4*)&B1[ss][tx*8 + 4];
            #pragma unroll
            for (int i = 0; i < 8; i++)
                #pragma unroll
                for (int j = 0; j < 8; j++)
                    accL[i][j] = fmaf(a[i], b[j], accL[i][j]);
        }
        __syncthreads();
    }
    // ---- phase 2: accL += PQ@S_prev; accM += PQ@M; denI += PQ.z_prev; denM += PQ.z
    const float* Qc = g_pq + (size_t)c * CHK * DIM;
    const float* Sp = g_kvprev + (size_t)c * DIM * DIM + eo;
    const float* Mp = Min + eo;
    const float* zp = g_ksprev + (size_t)c * DIM;
    for (int d0 = 0; d0 < DIM; d0 += 16) {
        #pragma unroll
        for (int it = 0; it < 4; it++) {
            int t = tid * 4 + it, tl = t >> 2, dl = (t & 3) * 4;
            float4 v = *(const float4*)(Qc + (size_t)tl * DIM + d0 + dl);
            Ts[dl+0][tl] = v.x; Ts[dl+1][tl] = v.y; Ts[dl+2][tl] = v.z; Ts[dl+3][tl] = v.w;
        }
        #pragma unroll
        for (int it = 0; it < 2; it++) {
            int t = tid * 2 + it, dl = t >> 4, el = (t & 15) * 4;
            *(float4*)&B1[dl][el] = *(const float4*)(Sp + (size_t)(d0 + dl) * DIM + el);
            *(float4*)&B2[dl][el] = *(const float4*)(Mp + (size_t)(d0 + dl) * DIM + el);
        }
        if (tid < 16) { Zp[tid] = zp[d0 + tid]; Zz[tid] = zin[d0 + tid]; }
        __syncthreads();
        #pragma unroll
        for (int dd = 0; dd < 16; dd++) {
            float a[8], bs[8], bm[8];
            *(float4*)(a)      = *(const float4*)&Ts[dd][ty*8];
            *(float4*)(a + 4)  = *(const float4*)&Ts[dd][ty*8 + 4];
            *(float4*)(bs)     = *(const float4*)&B1[dd][tx*8];
            *(float4*)(bs + 4) = *(const float4*)&B1[dd][tx*8 + 4];
            *(float4*)(bm)     = *(const float4*)&B2[dd][tx*8];
            *(float4*)(bm + 4) = *(const float4*)&B2[dd][tx*8 + 4];
            float zpv = Zp[dd], zzv = Zz[dd];
            #pragma unroll
            for (int i = 0; i < 8; i++) {
                denI[i] = fmaf(a[i], zpv, denI[i]);
                denM[i] = fmaf(a[i], zzv, denM[i]);
                #pragma unroll
                for (int j = 0; j < 8; j++) {
                    accL[i][j] = fmaf(a[i], bs[j], accL[i][j]);
                    accM[i][j] = fmaf(a[i], bm[j], accM[i][j]);
                }
            }
        }
        __syncthreads();
    }
    float gv = 1.f / (1.f + expf(-gate[0]));
    #pragma unroll
    for (int i = 0; i < 8; i++) {
        int tg = c * CHK + ty * 8 + i;
        float den  = g_den[tg] + denI[i] + EPSV;
        float mden = denM[i] + EPSV;
        float rl = (1.f - gv) / den, rm = gv / mden;
        float o[8];
        #pragma unroll
        for (int j = 0; j < 8; j++)
            o[j] = rm * accM[i][j] + rl * accL[i][j];
        *(float4*)(g_outbuf + (size_t)tg * DIM + eo + tx*8)     = *(float4*)(o);
        *(float4*)(g_outbuf + (size_t)tg * DIM + eo + tx*8 + 4) = *(float4*)(o + 4);
    }
}

// ======= Kernel 6: W = v - (PK@M)/(PK.z + eps)  (delta-rule retrieval) ==========
__global__ __launch_bounds__(128) void vret_kernel(
    const float* __restrict__ Min, const float* __restrict__ zin)
{
    __shared__ float Ts[16][132];
    __shared__ float B2[16][68];
    __shared__ float Zz[16];
    const int c = blockIdx.x;
    const int eo = blockIdx.y * 64;
    const int tid = threadIdx.x;
    const int ty = tid >> 3, tx = tid & 7;
    float acc[8][8], denV[8];
    #pragma unroll
    for (int i = 0; i < 8; i++) { denV[i] = 0.f;
        #pragma unroll
        for (int j = 0; j < 8; j++) acc[i][j] = 0.f; }

    const float* Kc = g_pk + (size_t)c * CHK * DIM;
    const float* Mp = Min + eo;
    for (int d0 = 0; d0 < DIM; d0 += 16) {
        #pragma unroll
        for (int it = 0; it < 4; it++) {
            int t = tid * 4 + it, tl = t >> 2, dl = (t & 3) * 4;
            float4 v = *(const float4*)(Kc + (size_t)tl * DIM + d0 + dl);
            Ts[dl+0][tl] = v.x; Ts[dl+1][tl] = v.y; Ts[dl+2][tl] = v.z; Ts[dl+3][tl] = v.w;
        }
        #pragma unroll
        for (int it = 0; it < 2; it++) {
            int t = tid * 2 + it, dl = t >> 4, el = (t & 15) * 4;
            *(float4*)&B2[dl][el] = *(const float4*)(Mp + (size_t)(d0 + dl) * DIM + el);
        }
        if (tid < 16) Zz[tid] = zin[d0 + tid];
        __syncthreads();
        #pragma unroll
        for (int dd = 0; dd < 16; dd++) {
            float a[8], bm[8];
            *(float4*)(a)      = *(const float4*)&Ts[dd][ty*8];
            *(float4*)(a + 4)  = *(const float4*)&Ts[dd][ty*8 + 4];
            *(float4*)(bm)     = *(const float4*)&B2[dd][tx*8];
            *(float4*)(bm + 4) = *(const float4*)&B2[dd][tx*8 + 4];
            float zzv = Zz[dd];
            #pragma unroll
            for (int i = 0; i < 8; i++) {
                denV[i] = fmaf(a[i], zzv, denV[i]);
                #pragma unroll
                for (int j = 0; j < 8; j++)
                    acc[i][j] = fmaf(a[i], bm[j], acc[i][j]);
            }
        }
        __syncthreads();
    }
    #pragma unroll
    for (int i = 0; i < 8; i++) {
        int tg = c * CHK + ty * 8 + i;
        float inv = 1.f / (denV[i] + EPSV);
        float4 v0 = *(const float4*)(g_v + (size_t)tg * DIM + eo + tx*8);
        float4 v1 = *(const float4*)(g_v + (size_t)tg * DIM + eo + tx*8 + 4);
        float o[8];
        o[0] = v0.x - acc[i][0]*inv; o[1] = v0.y - acc[i][1]*inv;
        o[2] = v0.z - acc[i][2]*inv; o[3] = v0.w - acc[i][3]*inv;
        o[4] = v1.x - acc[i][4]*inv; o[5] = v1.y - acc[i][5]*inv;
        o[6] = v1.z - acc[i][6]*inv; o[7] = v1.w - acc[i][7]*inv;
        *(float4*)(g_w + (size_t)tg * DIM + eo + tx*8)     = *(float4*)(o);
        *(float4*)(g_w + (size_t)tg * DIM + eo + tx*8 + 4) = *(float4*)(o + 4);
    }
}

// ============ Kernel 7: finalize M_new, z_new (deterministic reduction) =========
__global__ void finalize_kernel(const float* __restrict__ Min,
                                const float* __restrict__ zin,
                                float* __restrict__ outM, float* __restrict__ outZ)
{
    int p = blockIdx.x * 256 + threadIdx.x;   // 0..16383
    float s = Min[p];
    for (int cc = 0; cc < NC; cc++) s += g_mdelta[(size_t)cc * DIM * DIM + p];
    outM[p] = s;
    if (p < DIM) {
        float sz = zin[p];
        for (int cc = 0; cc < NC; cc++) sz += g_ks[cc * DIM + p];
        outZ[p] = sz;
    }
}

// ================= Kernel 8: output projection (NT GEMM, K=128) =================
__global__ __launch_bounds__(128) void outproj_kernel(
    const float* __restrict__ wo, float* __restrict__ out)
{
    __shared__ float As[16][68];
    __shared__ float Bs[16][132];
    const int m0 = blockIdx.x * 64;
    const int n0 = blockIdx.y * 128;
    const int tid = threadIdx.x;
    const int ty = tid >> 4, tx = tid & 15;
    float acc[8][8];
    #pragma unroll
    for (int i = 0; i < 8; i++)
        #pragma unroll
        for (int j = 0; j < 8; j++) acc[i][j] = 0.f;

    for (int k0 = 0; k0 < DIM; k0 += 16) {
        #pragma unroll
        for (int it = 0; it < 2; it++) {
            int t = tid * 2 + it, ml = t >> 2, kl = (t & 3) * 4;
            float4 v = *(const float4*)(g_outbuf + (size_t)(m0 + ml) * DIM + k0 + kl);
            As[kl+0][ml] = v.x; As[kl+1][ml] = v.y; As[kl+2][ml] = v.z; As[kl+3][ml] = v.w;
        }
        #pragma unroll
        for (int it = 0; it < 4; it++) {
            int t = tid * 4 + it, nl = t >> 2, kl = (t & 3) * 4;
            float4 v = *(const float4*)(wo + (size_t)(n0 + nl) * DIM + k0 + kl);
            Bs[kl+0][nl] = v.x; Bs[kl+1][nl] = v.y; Bs[kl+2][nl] = v.z; Bs[kl+3][nl] = v.w;
        }
        __syncthreads();
        #pragma unroll
        for (int kk = 0; kk < 16; kk++) {
            float a[8], b[8];
            *(float4*)(a)     = *(const float4*)&As[kk][ty*8];
            *(float4*)(a + 4) = *(const float4*)&As[kk][ty*8 + 4];
            *(float4*)(b)     = *(const float4*)&Bs[kk][tx*8];
            *(float4*)(b + 4) = *(const float4*)&Bs[kk][tx*8 + 4];
            #pragma unroll
            for (int i = 0; i < 8; i++)
                #pragma unroll
                for (int j = 0; j < 8; j++)
                    acc[i][j] = fmaf(a[i], b[j], acc[i][j]);
        }
        __syncthreads();
    }
    #pragma unroll
    for (int i = 0; i < 8; i++) {
        int m = m0 + ty * 8 + i;
        *(float4*)(out + (size_t)m * HID + n0 + tx*8)     = *(float4*)(acc[i]);
        *(float4*)(out + (size_t)m * HID + n0 + tx*8 + 4) = *(float4*)(acc[i] + 4);
    }
}

// =================================== launch =====================================
extern "C" void kernel_launch(void* const* d_in, const int* in_sizes, int n_in,
                              void* d_out, int out_size)
{
    const float* hs   = (const float*)d_in[0];
    const float* wq   = (const float*)d_in[1];
    const float* wk   = (const float*)d_in[2];
    const float* wv   = (const float*)d_in[3];
    const float* wo   = (const float*)d_in[4];
    const float* gate = (const float*)d_in[5];
    const float* M    = (const float*)d_in[6];
    const float* z    = (const float*)d_in[7];
    float* out  = (float*)d_out;
    float* outM = out + (size_t)TOK * HID;
    float* outZ = outM + DIM * DIM;

    qkv_kernel<<<dim3(TOK/64, 3), 128>>>(hs, wq, wk, wv);
    chunk_outer_kernel<<<NC, 256>>>(0);                       // g_kv, g_ks
    scan_kv_kernel<<<dim3(64, BATCH), 256>>>();               // S_prev
    scan_ks_kernel<<<BATCH, 128>>>();                         // z_prev
    scores_kernel<<<NC, 256>>>();                             // g_A, g_den
    output_kernel<<<dim3(NC, 2), 128>>>(M, z, gate);          // g_outbuf
    vret_kernel<<<dim3(NC, 2), 128>>>(M, z);                  // g_w
    chunk_outer_kernel<<<NC, 256>>>(1);                       // g_mdelta
    finalize_kernel<<<64, 256>>>(M, z, outM, outZ);           // M_new, z_new
    outproj_kernel<<<dim3(TOK/64, HID/128), 128>>>(wo, out);  // out
}